// round 2
// baseline (speedup 1.0000x reference)
#include <cuda_runtime.h>
#include <cuda_bf16.h>
#include <cstddef>

// ---------------- Problem constants (fixed by the reference) ----------------
#define N_NODES 50000
#define E_EDGES 800000
#define NFEAT   512
#define NH      256
#define NL      4
#define EVO     1024

// ---------------- Device-global scratch (no allocations allowed) ------------
__device__ float g_local0[(size_t)N_NODES * NH];          // relu(x @ fc0)
__device__ float g_h[(size_t)N_NODES * NH];               // dense transform per conv layer
__device__ float g_layers[(size_t)N_NODES * NL * NH];     // concat of 4 layer outputs
__device__ float g_glob[(size_t)N_NODES * NH];            // relu(evo @ fc1)
__device__ float g_local2[(size_t)N_NODES * NH];          // relu(layers @ fc2)

__device__ int   g_counts[N_NODES];
__device__ int   g_rowptr[N_NODES + 1];
__device__ int   g_cursor[N_NODES];
__device__ int   g_colidx[E_EDGES];
__device__ float g_vals[E_EDGES];

// ---------------- CSR build kernels ----------------------------------------
__global__ void k_zero_counts() {
    int i = blockIdx.x * blockDim.x + threadIdx.x;
    if (i < N_NODES) g_counts[i] = 0;
}

__global__ void k_hist(const int* __restrict__ dst) {
    int e = blockIdx.x * blockDim.x + threadIdx.x;
    if (e < E_EDGES) atomicAdd(&g_counts[dst[e]], 1);
}

// Single-block exclusive scan over g_counts -> g_rowptr, also seeds g_cursor.
__global__ void k_scan() {
    __shared__ int s[1024];
    __shared__ int s_carry;
    int t = threadIdx.x;
    if (t == 0) s_carry = 0;
    __syncthreads();
    for (int base = 0; base < N_NODES; base += 1024) {
        int i = base + t;
        int v = (i < N_NODES) ? g_counts[i] : 0;
        s[t] = v;
        __syncthreads();
        for (int d = 1; d < 1024; d <<= 1) {
            int x = (t >= d) ? s[t - d] : 0;
            __syncthreads();
            s[t] += x;
            __syncthreads();
        }
        int ex = s[t] - v;            // exclusive prefix within chunk
        int carry = s_carry;
        if (i < N_NODES) {
            g_rowptr[i] = carry + ex;
            g_cursor[i] = carry + ex;
        }
        __syncthreads();              // everyone done reading s_carry / s[1023]
        if (t == 0) s_carry = carry + s[1023];
        __syncthreads();
    }
    if (t == 0) g_rowptr[N_NODES] = s_carry;
}

__global__ void k_scatter(const int* __restrict__ src, const int* __restrict__ dst,
                          const float* __restrict__ w) {
    int e = blockIdx.x * blockDim.x + threadIdx.x;
    if (e < E_EDGES) {
        int d = dst[e];
        int pos = atomicAdd(&g_cursor[d], 1);
        g_colidx[pos] = src[e];
        g_vals[pos]   = w[e];
    }
}

// ---------------- SGEMM: C[M,256] = A[M,K] @ B[K,256] (+bias)(+C)(relu) ----
// BM=128, BN=128, BK=8, 256 threads, 8x8 micro-tile per thread.
template <bool RELU, bool ACC>
__global__ __launch_bounds__(256) void sgemm256(
    const float* __restrict__ A, int lda, int K,
    const float* __restrict__ B,           // ldb fixed = 256
    const float* __restrict__ bias,        // may be nullptr
    float* __restrict__ C, int ldc, int M)
{
    constexpr int BM = 128, BN = 128, BK = 8;
    __shared__ float As[BK][BM];
    __shared__ float Bs[BK][BN];

    const int t = threadIdx.x;
    const int row0 = blockIdx.y * BM;
    const int col0 = blockIdx.x * BN;
    const int tx = t & 15;        // 0..15  -> 8 cols each
    const int ty = t >> 4;        // 0..15  -> 8 rows each

    // A loader: thread t loads one float4: row am, cols ak..ak+3
    const int am = t >> 1;
    const int ak = (t & 1) * 4;
    // B loader: thread t loads one float4: row bk, cols bn..bn+3
    const int bk = t >> 5;
    const int bn = (t & 31) * 4;

    float acc[8][8];
#pragma unroll
    for (int i = 0; i < 8; i++)
#pragma unroll
        for (int j = 0; j < 8; j++) acc[i][j] = 0.f;

    for (int k0 = 0; k0 < K; k0 += BK) {
        const int arow = row0 + am;
        float4 av;
        if (arow < M) av = *(const float4*)(A + (size_t)arow * lda + k0 + ak);
        else          av = make_float4(0.f, 0.f, 0.f, 0.f);
        As[ak + 0][am] = av.x;
        As[ak + 1][am] = av.y;
        As[ak + 2][am] = av.z;
        As[ak + 3][am] = av.w;

        float4 bv = *(const float4*)(B + (size_t)(k0 + bk) * 256 + col0 + bn);
        *(float4*)&Bs[bk][bn] = bv;
        __syncthreads();

#pragma unroll
        for (int kk = 0; kk < BK; kk++) {
            float a[8], b[8];
            *(float4*)(a)     = *(const float4*)&As[kk][ty * 8];
            *(float4*)(a + 4) = *(const float4*)&As[kk][ty * 8 + 4];
            *(float4*)(b)     = *(const float4*)&Bs[kk][tx * 8];
            *(float4*)(b + 4) = *(const float4*)&Bs[kk][tx * 8 + 4];
#pragma unroll
            for (int i = 0; i < 8; i++)
#pragma unroll
                for (int j = 0; j < 8; j++) acc[i][j] += a[i] * b[j];
        }
        __syncthreads();
    }

    // Epilogue
#pragma unroll
    for (int i = 0; i < 8; i++) {
        const int r = row0 + ty * 8 + i;
        if (r < M) {
#pragma unroll
            for (int j = 0; j < 8; j += 4) {
                const int c = col0 + tx * 8 + j;
                float4 v = make_float4(acc[i][j], acc[i][j + 1], acc[i][j + 2], acc[i][j + 3]);
                if (ACC) {
                    float4 o = *(const float4*)(C + (size_t)r * ldc + c);
                    v.x += o.x; v.y += o.y; v.z += o.z; v.w += o.w;
                }
                if (bias) {
                    v.x += bias[c]; v.y += bias[c + 1]; v.z += bias[c + 2]; v.w += bias[c + 3];
                }
                if (RELU) {
                    v.x = fmaxf(v.x, 0.f); v.y = fmaxf(v.y, 0.f);
                    v.z = fmaxf(v.z, 0.f); v.w = fmaxf(v.w, 0.f);
                }
                *(float4*)(C + (size_t)r * ldc + c) = v;
            }
        }
    }
}

// ---------------- SpMM + ReLU: layers[:, layer*NH:(layer+1)*NH] -------------
// out[d,f] = relu( sum_{e in row d} w_e * h[src_e, f] )
__global__ void k_spmm_relu(const float* __restrict__ h, int layer) {
    const int d = blockIdx.x;
    const int f = threadIdx.x;                 // 256 threads = 256 features
    const int beg = g_rowptr[d];
    const int end = g_rowptr[d + 1];
    float acc = 0.f;
    for (int k = beg; k < end; k++) {
        const int   s = g_colidx[k];
        const float w = g_vals[k];
        acc += w * h[(size_t)s * NH + f];
    }
    g_layers[(size_t)d * (NL * NH) + layer * NH + f] = fmaxf(acc, 0.f);
}

// ---------------- Launch ----------------------------------------------------
extern "C" void kernel_launch(void* const* d_in, const int* in_sizes, int n_in,
                              void* d_out, int out_size)
{
    const float* x        = (const float*)d_in[0];   // [N, 512]
    const float* evo      = (const float*)d_in[1];   // [N, 1024]
    const int*   esrc     = (const int*)  d_in[2];   // [E]
    const int*   edst     = (const int*)  d_in[3];   // [E]
    const float* ew       = (const float*)d_in[4];   // [E]
    const float* conv_w   = (const float*)d_in[5];   // [4, 256, 256]
    const float* fc0_w    = (const float*)d_in[6];   // [512, 256]
    const float* fc0_b    = (const float*)d_in[7];
    const float* fc1_w    = (const float*)d_in[8];   // [1024, 256]
    const float* fc1_b    = (const float*)d_in[9];
    const float* fc2_w    = (const float*)d_in[10];  // [1024, 256]
    const float* fc2_b    = (const float*)d_in[11];
    const float* fc3_w    = (const float*)d_in[12];  // [512, 256]
    const float* fc3_b    = (const float*)d_in[13];
    float* out = (float*)d_out;

    float *p_local0, *p_h, *p_layers, *p_glob, *p_local2;
    cudaGetSymbolAddress((void**)&p_local0, g_local0);
    cudaGetSymbolAddress((void**)&p_h,      g_h);
    cudaGetSymbolAddress((void**)&p_layers, g_layers);
    cudaGetSymbolAddress((void**)&p_glob,   g_glob);
    cudaGetSymbolAddress((void**)&p_local2, g_local2);

    const dim3 gemm_grid(2, (N_NODES + 127) / 128);

    // --- CSR build (every call; deterministic work) ---
    k_zero_counts<<<(N_NODES + 255) / 256, 256>>>();
    k_hist<<<E_EDGES / 256, 256>>>(edst);
    k_scan<<<1, 1024>>>();
    k_scatter<<<E_EDGES / 256, 256>>>(esrc, edst, ew);

    // --- fc0: local0 = relu(x @ fc0_w + b) ---
    sgemm256<true, false><<<gemm_grid, 256>>>(x, NFEAT, NFEAT, fc0_w, fc0_b,
                                              p_local0, NH, N_NODES);

    // --- 4 GCN layers ---
    for (int i = 0; i < NL; i++) {
        const float* Ain = (i == 0) ? p_local0 : (p_layers + (i - 1) * NH);
        const int lda    = (i == 0) ? NH : (NL * NH);
        sgemm256<false, false><<<gemm_grid, 256>>>(Ain, lda, NH,
                                                   conv_w + (size_t)i * NH * NH, nullptr,
                                                   p_h, NH, N_NODES);
        k_spmm_relu<<<N_NODES, NH>>>(p_h, i);
    }

    // --- fc2: local2 = relu(layers @ fc2_w + b) ---
    sgemm256<true, false><<<gemm_grid, 256>>>(p_layers, NL * NH, NL * NH, fc2_w, fc2_b,
                                              p_local2, NH, N_NODES);

    // --- fc1: glob = relu(evo @ fc1_w + b) ---
    sgemm256<true, false><<<gemm_grid, 256>>>(evo, EVO, EVO, fc1_w, fc1_b,
                                              p_glob, NH, N_NODES);

    // --- fc3: out = relu(glob @ W_top + local2 @ W_bot + b) (split concat) ---
    sgemm256<false, false><<<gemm_grid, 256>>>(p_glob, NH, NH, fc3_w, fc3_b,
                                               out, NH, N_NODES);
    sgemm256<true, true><<<gemm_grid, 256>>>(p_local2, NH, NH, fc3_w + (size_t)NH * NH,
                                             nullptr, out, NH, N_NODES);
}

// round 3
// speedup vs baseline: 2.2257x; 2.2257x over previous
#include <cuda_runtime.h>
#include <cuda_bf16.h>
#include <cstddef>
#include <cstdint>

// ---------------- Problem constants (fixed by the reference) ----------------
#define N_NODES 50000
#define E_EDGES 800000
#define NFEAT   512
#define NH      256
#define NL      4
#define EVO     1024

// ---------------- Device-global scratch (no allocations allowed) ------------
__device__ float g_local0[(size_t)N_NODES * NH];          // relu(x @ fc0)
__device__ float g_h[(size_t)N_NODES * NH];               // dense transform per conv layer
__device__ float g_layers[(size_t)N_NODES * NL * NH];     // concat of 4 layer outputs
__device__ float g_glob[(size_t)N_NODES * NH];            // relu(evo @ fc1)
__device__ float g_local2[(size_t)N_NODES * NH];          // relu(layers @ fc2)

__device__ int   g_counts[N_NODES];
__device__ int   g_rowptr[N_NODES + 1];
__device__ int   g_cursor[N_NODES];
__device__ int   g_colidx[E_EDGES];
__device__ float g_vals[E_EDGES];

// ---------------- CSR build kernels ----------------------------------------
__global__ void k_zero_counts() {
    int i = blockIdx.x * blockDim.x + threadIdx.x;
    if (i < N_NODES) g_counts[i] = 0;
}

__global__ void k_hist(const int* __restrict__ dst) {
    int e = blockIdx.x * blockDim.x + threadIdx.x;
    if (e < E_EDGES) atomicAdd(&g_counts[dst[e]], 1);
}

// Single-block exclusive scan over g_counts -> g_rowptr, also seeds g_cursor.
__global__ void k_scan() {
    __shared__ int s[1024];
    __shared__ int s_carry;
    int t = threadIdx.x;
    if (t == 0) s_carry = 0;
    __syncthreads();
    for (int base = 0; base < N_NODES; base += 1024) {
        int i = base + t;
        int v = (i < N_NODES) ? g_counts[i] : 0;
        s[t] = v;
        __syncthreads();
        for (int d = 1; d < 1024; d <<= 1) {
            int x = (t >= d) ? s[t - d] : 0;
            __syncthreads();
            s[t] += x;
            __syncthreads();
        }
        int ex = s[t] - v;
        int carry = s_carry;
        if (i < N_NODES) {
            g_rowptr[i] = carry + ex;
            g_cursor[i] = carry + ex;
        }
        __syncthreads();
        if (t == 0) s_carry = carry + s[1023];
        __syncthreads();
    }
    if (t == 0) g_rowptr[N_NODES] = s_carry;
}

__global__ void k_scatter(const int* __restrict__ src, const int* __restrict__ dst,
                          const float* __restrict__ w) {
    int e = blockIdx.x * blockDim.x + threadIdx.x;
    if (e < E_EDGES) {
        int d = dst[e];
        int pos = atomicAdd(&g_cursor[d], 1);
        g_colidx[pos] = src[e];
        g_vals[pos]   = w[e];
    }
}

// ---------------- TF32 tensor-core GEMM -------------------------------------
// C[M,256] = A[M,K] @ B[K,256] (+bias)(+C)(relu)
// BM=128, BN=128, BK=32, 256 threads = 8 warps (2m x 4n), warp tile 64x32.
// mma.sync.m16n8k8 tf32, fp32 accumulate.

__device__ __forceinline__ uint32_t f2tf32(float x) {
    uint32_t u;
    asm("cvt.rna.tf32.f32 %0, %1;" : "=r"(u) : "f"(x));
    return u;
}

__device__ __forceinline__ void mma_tf32(float* d, const uint32_t* a, const uint32_t* b) {
    asm volatile(
        "mma.sync.aligned.m16n8k8.row.col.f32.tf32.tf32.f32 "
        "{%0,%1,%2,%3}, {%4,%5,%6,%7}, {%8,%9}, {%0,%1,%2,%3};\n"
        : "+f"(d[0]), "+f"(d[1]), "+f"(d[2]), "+f"(d[3])
        : "r"(a[0]), "r"(a[1]), "r"(a[2]), "r"(a[3]), "r"(b[0]), "r"(b[1]));
}

template <bool RELU, bool ACC>
__global__ __launch_bounds__(256) void tf32gemm(
    const float* __restrict__ A, int lda, int K,
    const float* __restrict__ B,            // ldb fixed = 256
    const float* __restrict__ bias,         // may be nullptr
    float* __restrict__ C, int ldc, int M)
{
    constexpr int BM = 128, BN = 128, BK = 32;
    constexpr int PA = BK + 4;              // 36: fragment reads conflict-free
    constexpr int PB = BN + 4;              // 132: fragment reads conflict-free
    __shared__ uint32_t As[BM * PA];        // [m][k] tf32 bits
    __shared__ uint32_t Bs[BK * PB];        // [k][n] tf32 bits

    const int t    = threadIdx.x;
    const int lane = t & 31;
    const int warp = t >> 5;
    const int row0 = blockIdx.y * BM;
    const int col0 = blockIdx.x * BN;
    const int m0w  = (warp & 1) * 64;       // warp m-offset
    const int n0w  = (warp >> 1) * 32;      // warp n-offset
    const int g    = lane >> 2;             // group id 0..7
    const int q    = lane & 3;              // thread-in-group 0..3

    float acc[4][4][4];
#pragma unroll
    for (int mi = 0; mi < 4; mi++)
#pragma unroll
        for (int ni = 0; ni < 4; ni++)
#pragma unroll
            for (int r = 0; r < 4; r++) acc[mi][ni][r] = 0.f;

    for (int k0 = 0; k0 < K; k0 += BK) {
        // Load A tile [BM x BK] (guard M tail), convert to tf32
#pragma unroll
        for (int i = 0; i < 4; i++) {
            const int f   = t + i * 256;    // float4 index, 8 per row
            const int row = f >> 3;
            const int kq  = (f & 7) * 4;
            float4 v;
            if (row0 + row < M) v = *(const float4*)(A + (size_t)(row0 + row) * lda + k0 + kq);
            else                v = make_float4(0.f, 0.f, 0.f, 0.f);
            uint32_t* p = &As[row * PA + kq];
            p[0] = f2tf32(v.x); p[1] = f2tf32(v.y); p[2] = f2tf32(v.z); p[3] = f2tf32(v.w);
        }
        // Load B tile [BK x BN], convert to tf32
#pragma unroll
        for (int i = 0; i < 4; i++) {
            const int f   = t + i * 256;    // float4 index, 32 per row
            const int row = f >> 5;
            const int nq  = (f & 31) * 4;
            float4 v = *(const float4*)(B + (size_t)(k0 + row) * 256 + col0 + nq);
            uint32_t* p = &Bs[row * PB + nq];
            p[0] = f2tf32(v.x); p[1] = f2tf32(v.y); p[2] = f2tf32(v.z); p[3] = f2tf32(v.w);
        }
        __syncthreads();

#pragma unroll
        for (int kk = 0; kk < BK; kk += 8) {
            uint32_t a[4][4], b[4][2];
#pragma unroll
            for (int mi = 0; mi < 4; mi++) {
                const int mr = m0w + mi * 16 + g;
                a[mi][0] = As[(mr    ) * PA + kk + q    ];
                a[mi][1] = As[(mr + 8) * PA + kk + q    ];
                a[mi][2] = As[(mr    ) * PA + kk + q + 4];
                a[mi][3] = As[(mr + 8) * PA + kk + q + 4];
            }
#pragma unroll
            for (int ni = 0; ni < 4; ni++) {
                const int nc = n0w + ni * 8 + g;
                b[ni][0] = Bs[(kk + q    ) * PB + nc];
                b[ni][1] = Bs[(kk + q + 4) * PB + nc];
            }
#pragma unroll
            for (int mi = 0; mi < 4; mi++)
#pragma unroll
                for (int ni = 0; ni < 4; ni++)
                    mma_tf32(acc[mi][ni], a[mi], b[ni]);
        }
        __syncthreads();
    }

    // Epilogue: c0,c1 at (row g, col 2q,2q+1); c2,c3 at (row g+8)
#pragma unroll
    for (int mi = 0; mi < 4; mi++) {
        const int r0 = row0 + m0w + mi * 16 + g;
        const int r1 = r0 + 8;
#pragma unroll
        for (int ni = 0; ni < 4; ni++) {
            const int c = col0 + n0w + ni * 8 + q * 2;
            float bx = 0.f, by = 0.f;
            if (bias) { bx = bias[c]; by = bias[c + 1]; }
#pragma unroll
            for (int half = 0; half < 2; half++) {
                const int r = half ? r1 : r0;
                if (r < M) {
                    float vx = acc[mi][ni][half * 2 + 0] + bx;
                    float vy = acc[mi][ni][half * 2 + 1] + by;
                    float* cp = C + (size_t)r * ldc + c;
                    if (ACC) { vx += cp[0]; vy += cp[1]; }
                    if (RELU) { vx = fmaxf(vx, 0.f); vy = fmaxf(vy, 0.f); }
                    *(float2*)cp = make_float2(vx, vy);
                }
            }
        }
    }
}

// ---------------- SpMM + ReLU: layers[:, layer*NH:(layer+1)*NH] -------------
__global__ void k_spmm_relu(const float* __restrict__ h, int layer) {
    const int d = blockIdx.x;
    const int f = threadIdx.x;                 // 256 threads = 256 features
    const int beg = g_rowptr[d];
    const int end = g_rowptr[d + 1];
    float acc = 0.f;
    for (int k = beg; k < end; k++) {
        const int   s = g_colidx[k];
        const float w = g_vals[k];
        acc += w * h[(size_t)s * NH + f];
    }
    g_layers[(size_t)d * (NL * NH) + layer * NH + f] = fmaxf(acc, 0.f);
}

// ---------------- Launch ----------------------------------------------------
extern "C" void kernel_launch(void* const* d_in, const int* in_sizes, int n_in,
                              void* d_out, int out_size)
{
    const float* x        = (const float*)d_in[0];   // [N, 512]
    const float* evo      = (const float*)d_in[1];   // [N, 1024]
    const int*   esrc     = (const int*)  d_in[2];   // [E]
    const int*   edst     = (const int*)  d_in[3];   // [E]
    const float* ew       = (const float*)d_in[4];   // [E]
    const float* conv_w   = (const float*)d_in[5];   // [4, 256, 256]
    const float* fc0_w    = (const float*)d_in[6];   // [512, 256]
    const float* fc0_b    = (const float*)d_in[7];
    const float* fc1_w    = (const float*)d_in[8];   // [1024, 256]
    const float* fc1_b    = (const float*)d_in[9];
    const float* fc2_w    = (const float*)d_in[10];  // [1024, 256]
    const float* fc2_b    = (const float*)d_in[11];
    const float* fc3_w    = (const float*)d_in[12];  // [512, 256]
    const float* fc3_b    = (const float*)d_in[13];
    float* out = (float*)d_out;

    float *p_local0, *p_h, *p_layers, *p_glob, *p_local2;
    cudaGetSymbolAddress((void**)&p_local0, g_local0);
    cudaGetSymbolAddress((void**)&p_h,      g_h);
    cudaGetSymbolAddress((void**)&p_layers, g_layers);
    cudaGetSymbolAddress((void**)&p_glob,   g_glob);
    cudaGetSymbolAddress((void**)&p_local2, g_local2);

    const dim3 gemm_grid(2, (N_NODES + 127) / 128);

    // --- CSR build ---
    k_zero_counts<<<(N_NODES + 255) / 256, 256>>>();
    k_hist<<<E_EDGES / 256, 256>>>(edst);
    k_scan<<<1, 1024>>>();
    k_scatter<<<E_EDGES / 256, 256>>>(esrc, edst, ew);

    // --- fc0: local0 = relu(x @ fc0_w + b) ---
    tf32gemm<true, false><<<gemm_grid, 256>>>(x, NFEAT, NFEAT, fc0_w, fc0_b,
                                              p_local0, NH, N_NODES);

    // --- 4 GCN layers ---
    for (int i = 0; i < NL; i++) {
        const float* Ain = (i == 0) ? p_local0 : (p_layers + (i - 1) * NH);
        const int lda    = (i == 0) ? NH : (NL * NH);
        tf32gemm<false, false><<<gemm_grid, 256>>>(Ain, lda, NH,
                                                   conv_w + (size_t)i * NH * NH, nullptr,
                                                   p_h, NH, N_NODES);
        k_spmm_relu<<<N_NODES, NH>>>(p_h, i);
    }

    // --- fc2: local2 = relu(layers @ fc2_w + b) ---
    tf32gemm<true, false><<<gemm_grid, 256>>>(p_layers, NL * NH, NL * NH, fc2_w, fc2_b,
                                              p_local2, NH, N_NODES);

    // --- fc1: glob = relu(evo @ fc1_w + b) ---
    tf32gemm<true, false><<<gemm_grid, 256>>>(evo, EVO, EVO, fc1_w, fc1_b,
                                              p_glob, NH, N_NODES);

    // --- fc3: out = relu(glob @ W_top + local2 @ W_bot + b) (split concat) ---
    tf32gemm<false, false><<<gemm_grid, 256>>>(p_glob, NH, NH, fc3_w, fc3_b,
                                               out, NH, N_NODES);
    tf32gemm<true, true><<<gemm_grid, 256>>>(p_local2, NH, NH, fc3_w + (size_t)NH * NH,
                                             nullptr, out, NH, N_NODES);
}

// round 4
// speedup vs baseline: 2.4428x; 1.0975x over previous
#include <cuda_runtime.h>
#include <cuda_bf16.h>
#include <cstddef>
#include <cstdint>

// ---------------- Problem constants (fixed by the reference) ----------------
#define N_NODES 50000
#define E_EDGES 800000
#define NFEAT   512
#define NH      256
#define NL      4
#define EVO     1024

// ---------------- Device-global scratch (no allocations allowed) ------------
__device__ float g_local0[(size_t)N_NODES * NH];          // relu(x @ fc0)
__device__ float g_h[(size_t)N_NODES * NH];               // dense transform per conv layer
__device__ float g_layers[(size_t)N_NODES * NL * NH];     // concat of 4 layer outputs
__device__ float g_glob[(size_t)N_NODES * NH];            // relu(evo @ fc1)
__device__ float g_local2[(size_t)N_NODES * NH];          // relu(layers @ fc2)

__device__ int   g_counts[N_NODES];
__device__ int   g_rowptr[N_NODES + 1];
__device__ int   g_cursor[N_NODES];
__device__ int   g_colidx[E_EDGES];
__device__ float g_vals[E_EDGES];

// ---------------- CSR build kernels ----------------------------------------
__global__ void k_zero_counts() {
    int i = blockIdx.x * blockDim.x + threadIdx.x;
    if (i < N_NODES) g_counts[i] = 0;
}

__global__ void k_hist(const int* __restrict__ dst) {
    int e = blockIdx.x * blockDim.x + threadIdx.x;
    if (e < E_EDGES) atomicAdd(&g_counts[dst[e]], 1);
}

// Single-block exclusive scan (warp-shuffle two-level, 3 syncs per chunk).
__global__ void k_scan() {
    __shared__ int warp_sums[32];
    __shared__ int s_carry;
    const int t = threadIdx.x, lane = t & 31, wid = t >> 5;
    if (t == 0) s_carry = 0;
    __syncthreads();
    for (int base = 0; base < N_NODES; base += 1024) {
        const int i = base + t;
        const int v = (i < N_NODES) ? g_counts[i] : 0;
        // inclusive warp scan
        int x = v;
#pragma unroll
        for (int d = 1; d < 32; d <<= 1) {
            int y = __shfl_up_sync(0xFFFFFFFFu, x, d);
            if (lane >= d) x += y;
        }
        if (lane == 31) warp_sums[wid] = x;
        __syncthreads();
        if (wid == 0) {
            int w = warp_sums[lane];
            int ws = w;
#pragma unroll
            for (int d = 1; d < 32; d <<= 1) {
                int y = __shfl_up_sync(0xFFFFFFFFu, ws, d);
                if (lane >= d) ws += y;
            }
            warp_sums[lane] = ws - w;   // exclusive warp offsets
        }
        __syncthreads();
        const int ex = x - v + warp_sums[wid];     // exclusive within chunk
        const int carry = s_carry;
        if (i < N_NODES) {
            g_rowptr[i] = carry + ex;
            g_cursor[i] = carry + ex;
        }
        __syncthreads();                            // all read s_carry
        if (t == 1023) s_carry = carry + ex + v;    // chunk total
        __syncthreads();
    }
    if (threadIdx.x == 0) g_rowptr[N_NODES] = s_carry;
}

__global__ void k_scatter(const int* __restrict__ src, const int* __restrict__ dst,
                          const float* __restrict__ w) {
    int e = blockIdx.x * blockDim.x + threadIdx.x;
    if (e < E_EDGES) {
        int d = dst[e];
        int pos = atomicAdd(&g_cursor[d], 1);
        g_colidx[pos] = src[e];
        g_vals[pos]   = w[e];
    }
}

// ---------------- TF32 tensor-core GEMM (double-buffered) -------------------
// C[M,256] = A[M,K] @ B[K,256] (+bias)(+C)(relu)
// BM=128, BN=128, BK=32, 256 threads = 8 warps (2m x 4n), warp tile 64x32.
// mma.sync.m16n8k8 tf32, fp32 accumulate. Dynamic smem: 2 buffers.

__device__ __forceinline__ uint32_t f2tf32(float x) {
    uint32_t u;
    asm("cvt.rna.tf32.f32 %0, %1;" : "=r"(u) : "f"(x));
    return u;
}

__device__ __forceinline__ void mma_tf32(float* d, const uint32_t* a, const uint32_t* b) {
    asm volatile(
        "mma.sync.aligned.m16n8k8.row.col.f32.tf32.tf32.f32 "
        "{%0,%1,%2,%3}, {%4,%5,%6,%7}, {%8,%9}, {%0,%1,%2,%3};\n"
        : "+f"(d[0]), "+f"(d[1]), "+f"(d[2]), "+f"(d[3])
        : "r"(a[0]), "r"(a[1]), "r"(a[2]), "r"(a[3]), "r"(b[0]), "r"(b[1]));
}

#define GEMM_BM 128
#define GEMM_BN 128
#define GEMM_BK 32
#define GEMM_PA 36      // A frag bank = (4g+q) mod 32 : bijection, conflict-free
#define GEMM_PB 136     // B frag bank = (8q+g) mod 32 : bijection, conflict-free
#define GEMM_SMEM ((2 * GEMM_BM * GEMM_PA + 2 * GEMM_BK * GEMM_PB) * 4)

template <bool RELU, bool ACC>
__global__ __launch_bounds__(256) void tf32gemm(
    const float* __restrict__ A, int lda, int K,
    const float* __restrict__ B,            // ldb fixed = 256
    const float* __restrict__ bias,         // may be nullptr
    float* __restrict__ C, int ldc, int M)
{
    constexpr int BM = GEMM_BM, BK = GEMM_BK;
    constexpr int PA = GEMM_PA, PB = GEMM_PB;
    extern __shared__ uint32_t dynsmem[];
    uint32_t* AsBase = dynsmem;                       // [2][BM*PA]
    uint32_t* BsBase = dynsmem + 2 * BM * PA;         // [2][BK*PB]

    const int t    = threadIdx.x;
    const int lane = t & 31;
    const int warp = t >> 5;
    const int row0 = blockIdx.y * BM;
    const int col0 = blockIdx.x * GEMM_BN;
    const int m0w  = (warp & 1) * 64;
    const int n0w  = (warp >> 1) * 32;
    const int g    = lane >> 2;
    const int q    = lane & 3;

    float acc[4][4][4];
#pragma unroll
    for (int mi = 0; mi < 4; mi++)
#pragma unroll
        for (int ni = 0; ni < 4; ni++)
#pragma unroll
            for (int r = 0; r < 4; r++) acc[mi][ni][r] = 0.f;

    float4 av[4], bv[4];
    const float4 zero4 = make_float4(0.f, 0.f, 0.f, 0.f);

    auto load_g = [&](int k0) {
#pragma unroll
        for (int i = 0; i < 4; i++) {
            const int f = t + i * 256;
            const int row = f >> 3, kq = (f & 7) * 4;
            av[i] = (row0 + row < M)
                  ? *(const float4*)(A + (size_t)(row0 + row) * lda + k0 + kq)
                  : zero4;
        }
#pragma unroll
        for (int i = 0; i < 4; i++) {
            const int f = t + i * 256;
            const int row = f >> 5, nq = (f & 31) * 4;
            bv[i] = *(const float4*)(B + (size_t)(k0 + row) * 256 + col0 + nq);
        }
    };
    auto store_s = [&](int buf) {
        uint32_t* as = AsBase + buf * BM * PA;
        uint32_t* bs = BsBase + buf * BK * PB;
#pragma unroll
        for (int i = 0; i < 4; i++) {
            const int f = t + i * 256;
            const int row = f >> 3, kq = (f & 7) * 4;
            uint32_t* p = &as[row * PA + kq];
            p[0] = f2tf32(av[i].x); p[1] = f2tf32(av[i].y);
            p[2] = f2tf32(av[i].z); p[3] = f2tf32(av[i].w);
        }
#pragma unroll
        for (int i = 0; i < 4; i++) {
            const int f = t + i * 256;
            const int row = f >> 5, nq = (f & 31) * 4;
            uint32_t* p = &bs[row * PB + nq];
            p[0] = f2tf32(bv[i].x); p[1] = f2tf32(bv[i].y);
            p[2] = f2tf32(bv[i].z); p[3] = f2tf32(bv[i].w);
        }
    };

    load_g(0);
    store_s(0);
    __syncthreads();

    int buf = 0;
    const int nk = K / BK;
    for (int it = 0; it < nk; it++) {
        if (it + 1 < nk) load_g((it + 1) * BK);   // gmem loads in flight during compute

        const uint32_t* as = AsBase + buf * BM * PA;
        const uint32_t* bs = BsBase + buf * BK * PB;
#pragma unroll
        for (int kk = 0; kk < BK; kk += 8) {
            uint32_t a[4][4], b[4][2];
#pragma unroll
            for (int mi = 0; mi < 4; mi++) {
                const int mr = m0w + mi * 16 + g;
                a[mi][0] = as[(mr    ) * PA + kk + q    ];
                a[mi][1] = as[(mr + 8) * PA + kk + q    ];
                a[mi][2] = as[(mr    ) * PA + kk + q + 4];
                a[mi][3] = as[(mr + 8) * PA + kk + q + 4];
            }
#pragma unroll
            for (int ni = 0; ni < 4; ni++) {
                const int nc = n0w + ni * 8 + g;
                b[ni][0] = bs[(kk + q    ) * PB + nc];
                b[ni][1] = bs[(kk + q + 4) * PB + nc];
            }
#pragma unroll
            for (int mi = 0; mi < 4; mi++)
#pragma unroll
                for (int ni = 0; ni < 4; ni++)
                    mma_tf32(acc[mi][ni], a[mi], b[ni]);
        }

        if (it + 1 < nk) {
            store_s(buf ^ 1);
            __syncthreads();
            buf ^= 1;
        }
    }

    // Epilogue: c0,c1 at (row g, col 2q,2q+1); c2,c3 at (row g+8)
#pragma unroll
    for (int mi = 0; mi < 4; mi++) {
        const int r0 = row0 + m0w + mi * 16 + g;
        const int r1 = r0 + 8;
#pragma unroll
        for (int ni = 0; ni < 4; ni++) {
            const int c = col0 + n0w + ni * 8 + q * 2;
            float bx = 0.f, by = 0.f;
            if (bias) { bx = bias[c]; by = bias[c + 1]; }
#pragma unroll
            for (int half = 0; half < 2; half++) {
                const int r = half ? r1 : r0;
                if (r < M) {
                    float vx = acc[mi][ni][half * 2 + 0] + bx;
                    float vy = acc[mi][ni][half * 2 + 1] + by;
                    float* cp = C + (size_t)r * ldc + c;
                    if (ACC) { vx += cp[0]; vy += cp[1]; }
                    if (RELU) { vx = fmaxf(vx, 0.f); vy = fmaxf(vy, 0.f); }
                    *(float2*)cp = make_float2(vx, vy);
                }
            }
        }
    }
}

// ---------------- SpMM + ReLU (float4, 4 rows per CTA) ----------------------
// out[d,f] = relu( sum_{e in row d} w_e * h[src_e, f] )
__global__ __launch_bounds__(256) void k_spmm_relu(const float* __restrict__ h, int layer) {
    const int sub = threadIdx.x >> 6;          // 0..3 : row within block
    const int f4  = threadIdx.x & 63;          // float4 lane: 64 x 4 = 256 feats
    const int d   = blockIdx.x * 4 + sub;      // 12500 * 4 = 50000 exact
    const int beg = g_rowptr[d];
    const int end = g_rowptr[d + 1];
    const float4* h4 = (const float4*)h;
    float4 acc = make_float4(0.f, 0.f, 0.f, 0.f);
    for (int k = beg; k < end; k++) {
        const int   s = g_colidx[k];
        const float w = g_vals[k];
        float4 v = h4[(size_t)s * 64 + f4];
        acc.x += w * v.x; acc.y += w * v.y; acc.z += w * v.z; acc.w += w * v.w;
    }
    float4 r = make_float4(fmaxf(acc.x, 0.f), fmaxf(acc.y, 0.f),
                           fmaxf(acc.z, 0.f), fmaxf(acc.w, 0.f));
    ((float4*)g_layers)[(size_t)d * (NL * NH / 4) + layer * 64 + f4] = r;
}

// ---------------- Launch ----------------------------------------------------
extern "C" void kernel_launch(void* const* d_in, const int* in_sizes, int n_in,
                              void* d_out, int out_size)
{
    const float* x        = (const float*)d_in[0];   // [N, 512]
    const float* evo      = (const float*)d_in[1];   // [N, 1024]
    const int*   esrc     = (const int*)  d_in[2];   // [E]
    const int*   edst     = (const int*)  d_in[3];   // [E]
    const float* ew       = (const float*)d_in[4];   // [E]
    const float* conv_w   = (const float*)d_in[5];   // [4, 256, 256]
    const float* fc0_w    = (const float*)d_in[6];   // [512, 256]
    const float* fc0_b    = (const float*)d_in[7];
    const float* fc1_w    = (const float*)d_in[8];   // [1024, 256]
    const float* fc1_b    = (const float*)d_in[9];
    const float* fc2_w    = (const float*)d_in[10];  // [1024, 256]
    const float* fc2_b    = (const float*)d_in[11];
    const float* fc3_w    = (const float*)d_in[12];  // [512, 256]
    const float* fc3_b    = (const float*)d_in[13];
    float* out = (float*)d_out;

    float *p_local0, *p_h, *p_layers, *p_glob, *p_local2;
    cudaGetSymbolAddress((void**)&p_local0, g_local0);
    cudaGetSymbolAddress((void**)&p_h,      g_h);
    cudaGetSymbolAddress((void**)&p_layers, g_layers);
    cudaGetSymbolAddress((void**)&p_glob,   g_glob);
    cudaGetSymbolAddress((void**)&p_local2, g_local2);

    // Allow >48KB dynamic smem for all used instantiations (idempotent).
    cudaFuncSetAttribute(tf32gemm<true,  false>,
                         cudaFuncAttributeMaxDynamicSharedMemorySize, GEMM_SMEM);
    cudaFuncSetAttribute(tf32gemm<false, false>,
                         cudaFuncAttributeMaxDynamicSharedMemorySize, GEMM_SMEM);
    cudaFuncSetAttribute(tf32gemm<true,  true>,
                         cudaFuncAttributeMaxDynamicSharedMemorySize, GEMM_SMEM);

    const dim3 gemm_grid(2, (N_NODES + 127) / 128);

    // --- CSR build ---
    k_zero_counts<<<(N_NODES + 255) / 256, 256>>>();
    k_hist<<<E_EDGES / 256, 256>>>(edst);
    k_scan<<<1, 1024>>>();
    k_scatter<<<E_EDGES / 256, 256>>>(esrc, edst, ew);

    // --- fc0: local0 = relu(x @ fc0_w + b) ---
    tf32gemm<true, false><<<gemm_grid, 256, GEMM_SMEM>>>(
        x, NFEAT, NFEAT, fc0_w, fc0_b, p_local0, NH, N_NODES);

    // --- 4 GCN layers ---
    for (int i = 0; i < NL; i++) {
        const float* Ain = (i == 0) ? p_local0 : (p_layers + (i - 1) * NH);
        const int lda    = (i == 0) ? NH : (NL * NH);
        tf32gemm<false, false><<<gemm_grid, 256, GEMM_SMEM>>>(
            Ain, lda, NH, conv_w + (size_t)i * NH * NH, nullptr, p_h, NH, N_NODES);
        k_spmm_relu<<<N_NODES / 4, 256>>>(p_h, i);
    }

    // --- fc2: local2 = relu(layers @ fc2_w + b) ---
    tf32gemm<true, false><<<gemm_grid, 256, GEMM_SMEM>>>(
        p_layers, NL * NH, NL * NH, fc2_w, fc2_b, p_local2, NH, N_NODES);

    // --- fc1: glob = relu(evo @ fc1_w + b) ---
    tf32gemm<true, false><<<gemm_grid, 256, GEMM_SMEM>>>(
        evo, EVO, EVO, fc1_w, fc1_b, p_glob, NH, N_NODES);

    // --- fc3: out = relu(glob @ W_top + local2 @ W_bot + b) (split concat) ---
    tf32gemm<false, false><<<gemm_grid, 256, GEMM_SMEM>>>(
        p_glob, NH, NH, fc3_w, fc3_b, out, NH, N_NODES);
    tf32gemm<true, true><<<gemm_grid, 256, GEMM_SMEM>>>(
        p_local2, NH, NH, fc3_w + (size_t)NH * NH, nullptr, out, NH, N_NODES);
}

// round 5
// speedup vs baseline: 3.0666x; 1.2554x over previous
#include <cuda_runtime.h>
#include <cuda_bf16.h>
#include <cstddef>
#include <cstdint>

// ---------------- Problem constants (fixed by the reference) ----------------
#define N_NODES 50000
#define E_EDGES 800000
#define NFEAT   512
#define NH      256
#define NL      4
#define EVO     1024

// ---------------- Device-global scratch (no allocations allowed) ------------
__device__ float g_local0[(size_t)N_NODES * NH];          // relu(x @ fc0)
__device__ float g_h[(size_t)N_NODES * NH];               // dense transform per conv layer
__device__ float g_layers[(size_t)N_NODES * NL * NH];     // concat of 4 layer outputs
__device__ float g_glob[(size_t)N_NODES * NH];            // relu(evo @ fc1)
__device__ float g_local2[(size_t)N_NODES * NH];          // relu(layers @ fc2)

__device__ int   g_counts[N_NODES];
__device__ int   g_rowptr[N_NODES + 1];
__device__ int   g_cursor[N_NODES];
__device__ int   g_colidx[E_EDGES];
__device__ float g_vals[E_EDGES];

// ---------------- CSR build kernels ----------------------------------------
__global__ void k_zero_counts() {
    int i = blockIdx.x * blockDim.x + threadIdx.x;
    if (i < N_NODES) g_counts[i] = 0;
}

__global__ void k_hist(const int* __restrict__ dst) {
    int e = blockIdx.x * blockDim.x + threadIdx.x;
    if (e < E_EDGES) atomicAdd(&g_counts[dst[e]], 1);
}

// Single-block exclusive scan (warp-shuffle two-level, 3 syncs per chunk).
__global__ void k_scan() {
    __shared__ int warp_sums[32];
    __shared__ int s_carry;
    const int t = threadIdx.x, lane = t & 31, wid = t >> 5;
    if (t == 0) s_carry = 0;
    __syncthreads();
    for (int base = 0; base < N_NODES; base += 1024) {
        const int i = base + t;
        const int v = (i < N_NODES) ? g_counts[i] : 0;
        int x = v;
#pragma unroll
        for (int d = 1; d < 32; d <<= 1) {
            int y = __shfl_up_sync(0xFFFFFFFFu, x, d);
            if (lane >= d) x += y;
        }
        if (lane == 31) warp_sums[wid] = x;
        __syncthreads();
        if (wid == 0) {
            int w = warp_sums[lane];
            int ws = w;
#pragma unroll
            for (int d = 1; d < 32; d <<= 1) {
                int y = __shfl_up_sync(0xFFFFFFFFu, ws, d);
                if (lane >= d) ws += y;
            }
            warp_sums[lane] = ws - w;
        }
        __syncthreads();
        const int ex = x - v + warp_sums[wid];
        const int carry = s_carry;
        if (i < N_NODES) {
            g_rowptr[i] = carry + ex;
            g_cursor[i] = carry + ex;
        }
        __syncthreads();
        if (t == 1023) s_carry = carry + ex + v;
        __syncthreads();
    }
    if (threadIdx.x == 0) g_rowptr[N_NODES] = s_carry;
}

__global__ void k_scatter(const int* __restrict__ src, const int* __restrict__ dst,
                          const float* __restrict__ w) {
    int e = blockIdx.x * blockDim.x + threadIdx.x;
    if (e < E_EDGES) {
        int d = dst[e];
        int pos = atomicAdd(&g_cursor[d], 1);
        g_colidx[pos] = src[e];
        g_vals[pos]   = w[e];
    }
}

// ---------------- TF32 tensor-core GEMM (cp.async 3-stage pipeline) ---------
// C[M,256] = A[M,K] @ B[K,256] (+bias)(+relu), optional concat-A2 at k=256.
// BM=128, BN=128, BK=32, 256 threads = 8 warps (2m x 4n), warp tile 64x32.
// smem holds fp32; cvt to tf32 at fragment-load. mma.sync.m16n8k8.

__device__ __forceinline__ uint32_t f2tf32(float x) {
    uint32_t u;
    asm("cvt.rna.tf32.f32 %0, %1;" : "=r"(u) : "f"(x));
    return u;
}

__device__ __forceinline__ void mma_tf32(float* d, const uint32_t* a, const uint32_t* b) {
    asm volatile(
        "mma.sync.aligned.m16n8k8.row.col.f32.tf32.tf32.f32 "
        "{%0,%1,%2,%3}, {%4,%5,%6,%7}, {%8,%9}, {%0,%1,%2,%3};\n"
        : "+f"(d[0]), "+f"(d[1]), "+f"(d[2]), "+f"(d[3])
        : "r"(a[0]), "r"(a[1]), "r"(a[2]), "r"(a[3]), "r"(b[0]), "r"(b[1]));
}

__device__ __forceinline__ void cp16(uint32_t dst_s, const void* src, bool valid) {
    int sz = valid ? 16 : 0;
    asm volatile("cp.async.cg.shared.global [%0], [%1], 16, %2;\n"
                 :: "r"(dst_s), "l"(src), "r"(sz));
}

#define GEMM_BM 128
#define GEMM_BN 128
#define GEMM_BK 32
#define GEMM_PA 36      // A frag bank = (4g+q) mod 32 : bijection, conflict-free
#define GEMM_PB 136     // B frag bank = (8q+g) mod 32 : bijection, conflict-free
#define GEMM_STAGES 3
#define GEMM_STG_U32 (GEMM_BM * GEMM_PA + GEMM_BK * GEMM_PB)
#define GEMM_SMEM (GEMM_STAGES * GEMM_STG_U32 * 4)

template <bool RELU, bool CONCAT>
__global__ __launch_bounds__(256, 2) void tf32gemm(
    const float* __restrict__ A, int lda, int K,
    const float* __restrict__ A2,           // CONCAT: second source at k>=256 (lda=256)
    const float* __restrict__ B,            // ldb fixed = 256
    const float* __restrict__ bias,         // may be nullptr
    float* __restrict__ C, int ldc, int M)
{
    constexpr int BM = GEMM_BM, BK = GEMM_BK;
    constexpr int PA = GEMM_PA, PB = GEMM_PB;
    extern __shared__ float dynsmem[];

    const int t    = threadIdx.x;
    const int lane = t & 31;
    const int warp = t >> 5;
    const int row0 = blockIdx.y * BM;
    const int col0 = blockIdx.x * GEMM_BN;
    const int m0w  = (warp & 1) * 64;
    const int n0w  = (warp >> 1) * 32;
    const int g    = lane >> 2;
    const int q    = lane & 3;

    const uint32_t smem_u = (uint32_t)__cvta_generic_to_shared(dynsmem);

    float acc[4][4][4];
#pragma unroll
    for (int mi = 0; mi < 4; mi++)
#pragma unroll
        for (int ni = 0; ni < 4; ni++)
#pragma unroll
            for (int r = 0; r < 4; r++) acc[mi][ni][r] = 0.f;

    // Precomputed per-thread loader coords
    const int a_row = t >> 1;              // f = t+i*256: row = f>>3 -> t>>3 + i*32? No:
    // A loader: f = t + i*256, row = f>>3, kq = (f&7)*4.  (t>>3 + i*32, same kq for all i)
    const int ar0 = t >> 3;                // base row, +32 per i
    const int akq = (t & 7) * 4;
    // B loader: f = t + i*256, row = f>>5 (t>>5 + i*8), nq = (f&31)*4
    const int br0 = t >> 5;
    const int bnq = (t & 31) * 4;
    (void)a_row;

    auto issue = [&](int buf, int stage_idx) {
        const int k0 = stage_idx * BK;
        const uint32_t as_u = smem_u + (uint32_t)(buf * GEMM_STG_U32) * 4u;
        const uint32_t bs_u = as_u + (uint32_t)(BM * PA) * 4u;
        const float* Asel = A;
        int kbase = k0;
        if (CONCAT && k0 >= 256) { Asel = A2; kbase = k0 - 256; }
#pragma unroll
        for (int i = 0; i < 4; i++) {
            const int row = ar0 + i * 32;
            const bool valid = (row0 + row) < M;
            const int rclamp = valid ? (row0 + row) : (M - 1);
            cp16(as_u + (uint32_t)(row * PA + akq) * 4u,
                 Asel + (size_t)rclamp * lda + kbase + akq, valid);
        }
#pragma unroll
        for (int i = 0; i < 4; i++) {
            const int row = br0 + i * 8;
            cp16(bs_u + (uint32_t)(row * PB + bnq) * 4u,
                 B + (size_t)(k0 + row) * 256 + col0 + bnq, true);
        }
    };

    auto compute = [&](int buf) {
        const float* as = dynsmem + buf * GEMM_STG_U32;
        const float* bs = as + BM * PA;
#pragma unroll
        for (int kk = 0; kk < BK; kk += 8) {
            uint32_t a[4][4], b[4][2];
#pragma unroll
            for (int mi = 0; mi < 4; mi++) {
                const int mr = m0w + mi * 16 + g;
                a[mi][0] = f2tf32(as[(mr    ) * PA + kk + q    ]);
                a[mi][1] = f2tf32(as[(mr + 8) * PA + kk + q    ]);
                a[mi][2] = f2tf32(as[(mr    ) * PA + kk + q + 4]);
                a[mi][3] = f2tf32(as[(mr + 8) * PA + kk + q + 4]);
            }
#pragma unroll
            for (int ni = 0; ni < 4; ni++) {
                const int nc = n0w + ni * 8 + g;
                b[ni][0] = f2tf32(bs[(kk + q    ) * PB + nc]);
                b[ni][1] = f2tf32(bs[(kk + q + 4) * PB + nc]);
            }
#pragma unroll
            for (int mi = 0; mi < 4; mi++)
#pragma unroll
                for (int ni = 0; ni < 4; ni++)
                    mma_tf32(acc[mi][ni], a[mi], b[ni]);
        }
    };

    const int nk = K / BK;

    // Prologue: fill first STAGES-1 stages
#pragma unroll
    for (int s = 0; s < GEMM_STAGES - 1; s++) {
        if (s < nk) issue(s, s);
        asm volatile("cp.async.commit_group;\n");
    }

    for (int it = 0; it < nk; it++) {
        asm volatile("cp.async.wait_group %0;\n" :: "n"(GEMM_STAGES - 2));
        __syncthreads();                      // stage `it` visible; compute(it-1) done by all
        const int nxt = it + GEMM_STAGES - 1;
        if (nxt < nk) issue(nxt % GEMM_STAGES, nxt);
        asm volatile("cp.async.commit_group;\n");
        compute(it % GEMM_STAGES);
        __syncthreads();                      // done reading stage `it` before its reuse
    }

    // Epilogue: c0,c1 at (row g, col 2q,2q+1); c2,c3 at (row g+8)
#pragma unroll
    for (int mi = 0; mi < 4; mi++) {
        const int r0 = row0 + m0w + mi * 16 + g;
        const int r1 = r0 + 8;
#pragma unroll
        for (int ni = 0; ni < 4; ni++) {
            const int c = col0 + n0w + ni * 8 + q * 2;
            float bx = 0.f, by = 0.f;
            if (bias) { bx = bias[c]; by = bias[c + 1]; }
#pragma unroll
            for (int half = 0; half < 2; half++) {
                const int r = half ? r1 : r0;
                if (r < M) {
                    float vx = acc[mi][ni][half * 2 + 0] + bx;
                    float vy = acc[mi][ni][half * 2 + 1] + by;
                    if (RELU) { vx = fmaxf(vx, 0.f); vy = fmaxf(vy, 0.f); }
                    *(float2*)(C + (size_t)r * ldc + c) = make_float2(vx, vy);
                }
            }
        }
    }
}

// ---------------- SpMM + ReLU (float4, 4 rows per CTA) ----------------------
__global__ __launch_bounds__(256) void k_spmm_relu(const float* __restrict__ h, int layer) {
    const int sub = threadIdx.x >> 6;          // 0..3 : row within block
    const int f4  = threadIdx.x & 63;          // float4 lane: 64 x 4 = 256 feats
    const int d   = blockIdx.x * 4 + sub;      // 12500 * 4 = 50000 exact
    const int beg = g_rowptr[d];
    const int end = g_rowptr[d + 1];
    const float4* h4 = (const float4*)h;
    float4 acc = make_float4(0.f, 0.f, 0.f, 0.f);
    for (int k = beg; k < end; k++) {
        const int   s = g_colidx[k];
        const float w = g_vals[k];
        float4 v = h4[(size_t)s * 64 + f4];
        acc.x += w * v.x; acc.y += w * v.y; acc.z += w * v.z; acc.w += w * v.w;
    }
    float4 r = make_float4(fmaxf(acc.x, 0.f), fmaxf(acc.y, 0.f),
                           fmaxf(acc.z, 0.f), fmaxf(acc.w, 0.f));
    ((float4*)g_layers)[(size_t)d * (NL * NH / 4) + layer * 64 + f4] = r;
}

// ---------------- Launch ----------------------------------------------------
extern "C" void kernel_launch(void* const* d_in, const int* in_sizes, int n_in,
                              void* d_out, int out_size)
{
    const float* x        = (const float*)d_in[0];   // [N, 512]
    const float* evo      = (const float*)d_in[1];   // [N, 1024]
    const int*   esrc     = (const int*)  d_in[2];   // [E]
    const int*   edst     = (const int*)  d_in[3];   // [E]
    const float* ew       = (const float*)d_in[4];   // [E]
    const float* conv_w   = (const float*)d_in[5];   // [4, 256, 256]
    const float* fc0_w    = (const float*)d_in[6];   // [512, 256]
    const float* fc0_b    = (const float*)d_in[7];
    const float* fc1_w    = (const float*)d_in[8];   // [1024, 256]
    const float* fc1_b    = (const float*)d_in[9];
    const float* fc2_w    = (const float*)d_in[10];  // [1024, 256]
    const float* fc2_b    = (const float*)d_in[11];
    const float* fc3_w    = (const float*)d_in[12];  // [512, 256]
    const float* fc3_b    = (const float*)d_in[13];
    float* out = (float*)d_out;

    float *p_local0, *p_h, *p_layers, *p_glob, *p_local2;
    cudaGetSymbolAddress((void**)&p_local0, g_local0);
    cudaGetSymbolAddress((void**)&p_h,      g_h);
    cudaGetSymbolAddress((void**)&p_layers, g_layers);
    cudaGetSymbolAddress((void**)&p_glob,   g_glob);
    cudaGetSymbolAddress((void**)&p_local2, g_local2);

    cudaFuncSetAttribute(tf32gemm<true,  false>,
                         cudaFuncAttributeMaxDynamicSharedMemorySize, GEMM_SMEM);
    cudaFuncSetAttribute(tf32gemm<false, false>,
                         cudaFuncAttributeMaxDynamicSharedMemorySize, GEMM_SMEM);
    cudaFuncSetAttribute(tf32gemm<true,  true>,
                         cudaFuncAttributeMaxDynamicSharedMemorySize, GEMM_SMEM);

    const dim3 gemm_grid(2, (N_NODES + 127) / 128);

    // --- CSR build ---
    k_zero_counts<<<(N_NODES + 255) / 256, 256>>>();
    k_hist<<<E_EDGES / 256, 256>>>(edst);
    k_scan<<<1, 1024>>>();
    k_scatter<<<E_EDGES / 256, 256>>>(esrc, edst, ew);

    // --- fc0: local0 = relu(x @ fc0_w + b) ---
    tf32gemm<true, false><<<gemm_grid, 256, GEMM_SMEM>>>(
        x, NFEAT, NFEAT, nullptr, fc0_w, fc0_b, p_local0, NH, N_NODES);

    // --- 4 GCN layers ---
    for (int i = 0; i < NL; i++) {
        const float* Ain = (i == 0) ? p_local0 : (p_layers + (i - 1) * NH);
        const int lda    = (i == 0) ? NH : (NL * NH);
        tf32gemm<false, false><<<gemm_grid, 256, GEMM_SMEM>>>(
            Ain, lda, NH, nullptr, conv_w + (size_t)i * NH * NH, nullptr, p_h, NH, N_NODES);
        k_spmm_relu<<<N_NODES / 4, 256>>>(p_h, i);
    }

    // --- fc2: local2 = relu(layers @ fc2_w + b) ---
    tf32gemm<true, false><<<gemm_grid, 256, GEMM_SMEM>>>(
        p_layers, NL * NH, NL * NH, nullptr, fc2_w, fc2_b, p_local2, NH, N_NODES);

    // --- fc1: glob = relu(evo @ fc1_w + b) ---
    tf32gemm<true, false><<<gemm_grid, 256, GEMM_SMEM>>>(
        evo, EVO, EVO, nullptr, fc1_w, fc1_b, p_glob, NH, N_NODES);

    // --- fc3 (fused concat): out = relu([glob | local2] @ fc3_w + b) ---
    tf32gemm<true, true><<<gemm_grid, 256, GEMM_SMEM>>>(
        p_glob, NH, 2 * NH, p_local2, fc3_w, fc3_b, out, NH, N_NODES);
}